// round 3
// baseline (speedup 1.0000x reference)
#include <cuda_runtime.h>
#include <cuda_fp16.h>

#define N_NODES 100000
#define N_EDGES 1000000
#define NB_SCAN 98      // ceil(100000 / 1024)

__device__ __half g_t[N_NODES * 64];     // [n][o][c] fp16
__device__ __half g_tb[N_NODES * 16];    // [n][o]    fp16
__device__ float  g_r[N_NODES * 16];     // [n][o]    fp32: v@root + bias
__device__ int    g_deg[N_NODES];
__device__ int    g_rowstart[N_NODES];
__device__ int    g_cursor[N_NODES];
__device__ int    g_blocksum[NB_SCAN];
__device__ uint2  g_perm[N_EDGES];       // {src, eid} sorted by dst
__device__ float  g_s1[16];
__device__ float  g_s2[16];

// ---------------------------------------------------------------------------
// K0: zero degree histogram + BN stats
// ---------------------------------------------------------------------------
__global__ void __launch_bounds__(256) k_zero() {
    int idx = blockIdx.x * 256 + threadIdx.x;
    if (idx < N_NODES) g_deg[idx] = 0;
    if (idx < 16) { g_s1[idx] = 0.0f; g_s2[idx] = 0.0f; }
}

// ---------------------------------------------------------------------------
// K1: per-node precompute of t (fp16), tb (fp16), r = v@root + bias (fp32).
// ---------------------------------------------------------------------------
__global__ void __launch_bounds__(256) k_node_pre(
    const float* __restrict__ v,
    const float* __restrict__ enet_w,   // [256][4]
    const float* __restrict__ enet_b,   // [256]
    const float* __restrict__ root,     // [16][16] (i,o)
    const float* __restrict__ bias)     // [16]
{
    __shared__ float sw[1024];
    __shared__ float sb[256];
    __shared__ float sroot[256];
    __shared__ float sv[256];
    int t = threadIdx.x;
    for (int i = t; i < 1024; i += 256) sw[i] = enet_w[i];
    sb[t] = enet_b[t];
    sroot[t] = root[t];
    int nbase = blockIdx.x * 16;
    sv[t] = v[nbase * 16 + t];
    __syncthreads();

    int nl = t >> 4;
    int o = t & 15;
    int n = nbase + nl;
    if (n >= N_NODES) return;

    float a0 = 0.f, a1 = 0.f, a2 = 0.f, a3 = 0.f, ab = 0.f, ar = bias[o];
    const float* vrow = sv + nl * 16;
#pragma unroll
    for (int i = 0; i < 16; i++) {
        float vi = vrow[i];
        int j = i * 16 + o;
        const float* w4 = sw + j * 4;
        a0 = fmaf(vi, w4[0], a0);
        a1 = fmaf(vi, w4[1], a1);
        a2 = fmaf(vi, w4[2], a2);
        a3 = fmaf(vi, w4[3], a3);
        ab = fmaf(vi, sb[j], ab);
        ar = fmaf(vi, sroot[j], ar);
    }
    __half2 h01 = __floats2half2_rn(a0, a1);
    __half2 h23 = __floats2half2_rn(a2, a3);
    uint2 pk;
    pk.x = *reinterpret_cast<unsigned*>(&h01);
    pk.y = *reinterpret_cast<unsigned*>(&h23);
    *reinterpret_cast<uint2*>(g_t + (size_t)n * 64 + o * 4) = pk;
    g_tb[n * 16 + o] = __float2half_rn(ab);
    g_r[n * 16 + o] = ar;
}

// ---------------------------------------------------------------------------
// K2: degree histogram over dst
// ---------------------------------------------------------------------------
__global__ void __launch_bounds__(256) k_hist(const int* __restrict__ ei) {
    int e = blockIdx.x * 256 + threadIdx.x;
    if (e < N_EDGES) atomicAdd(&g_deg[ei[N_EDGES + e]], 1);
}

// ---------------------------------------------------------------------------
// K3: per-block exclusive scan of degrees (1024-elem chunks)
// ---------------------------------------------------------------------------
__global__ void __launch_bounds__(1024) k_scan1() {
    __shared__ int s[1024];
    int t = threadIdx.x;
    int i = blockIdx.x * 1024 + t;
    int v = (i < N_NODES) ? g_deg[i] : 0;
    s[t] = v;
    __syncthreads();
#pragma unroll
    for (int off = 1; off < 1024; off <<= 1) {
        int x = (t >= off) ? s[t - off] : 0;
        __syncthreads();
        s[t] += x;
        __syncthreads();
    }
    if (i < N_NODES) g_rowstart[i] = s[t] - v;     // exclusive
    if (t == 1023) g_blocksum[blockIdx.x] = s[t];
}

// ---------------------------------------------------------------------------
// K4: add cross-block offsets; materialize rowstart + cursor
// ---------------------------------------------------------------------------
__global__ void __launch_bounds__(1024) k_fixup() {
    __shared__ int sb[128];
    int b = blockIdx.x;
    int t = threadIdx.x;
    if (t < 128) sb[t] = (t < b && t < NB_SCAN) ? g_blocksum[t] : 0;
    __syncthreads();
#pragma unroll
    for (int s = 64; s >= 1; s >>= 1) {
        if (t < s) sb[t] += sb[t + s];
        __syncthreads();
    }
    int i = b * 1024 + t;
    if (i < N_NODES) {
        int rs = g_rowstart[i] + sb[0];
        g_rowstart[i] = rs;
        g_cursor[i] = rs;
    }
}

// ---------------------------------------------------------------------------
// K5: scatter {src, eid} into dst-sorted perm array
// ---------------------------------------------------------------------------
__global__ void __launch_bounds__(256) k_scatter(const int* __restrict__ ei) {
    int e = blockIdx.x * 256 + threadIdx.x;
    if (e >= N_EDGES) return;
    int src = ei[e];
    int dst = ei[N_EDGES + e];
    int pos = atomicAdd(&g_cursor[dst], 1);
    g_perm[pos] = make_uint2((unsigned)src, (unsigned)e);
}

// ---------------------------------------------------------------------------
// K6: gather — 8 threads per node, each accumulates outputs o=2j, 2j+1.
// Replaces edge-RED + finalize: out = msg_sum/max(deg,1) + r; BN stats inline.
// ---------------------------------------------------------------------------
__global__ void __launch_bounds__(256) k_gather(
    const float* __restrict__ efeat,
    float* __restrict__ out)
{
    int t = threadIdx.x;
    int gid = blockIdx.x * 256 + t;
    int n = gid >> 3;
    int j = gid & 7;          // == t & 7 (256 % 8 == 0)

    float a0 = 0.f, a1 = 0.f;
    int beg = 0, deg = 0;
    if (n < N_NODES) { beg = g_rowstart[n]; deg = g_deg[n]; }
    int end = beg + deg;

    const float4* ef4 = reinterpret_cast<const float4*>(efeat);

    uint2 es = (deg > 0) ? g_perm[beg] : make_uint2(0u, 0u);
    for (int p = beg; p < end; p++) {
        uint2 cur = es;
        int pn = p + 1;
        if (pn < end) es = g_perm[pn];                 // prefetch next
        float4 ev = __ldg(ef4 + cur.y);
        uint4 traw = __ldg(reinterpret_cast<const uint4*>(g_t + (size_t)cur.x * 64 + j * 8));
        unsigned tbraw = __ldg(reinterpret_cast<const unsigned*>(g_tb + (size_t)cur.x * 16 + j * 2));
        __half2 h0 = *reinterpret_cast<__half2*>(&traw.x);
        __half2 h1 = *reinterpret_cast<__half2*>(&traw.y);
        __half2 h2 = *reinterpret_cast<__half2*>(&traw.z);
        __half2 h3 = *reinterpret_cast<__half2*>(&traw.w);
        __half2 tbh = *reinterpret_cast<__half2*>(&tbraw);
        float2 c0 = __half22float2(h0);
        float2 c1 = __half22float2(h1);
        float2 c2 = __half22float2(h2);
        float2 c3 = __half22float2(h3);
        float2 tbf = __half22float2(tbh);
        a0 += fmaf(ev.x, c0.x, fmaf(ev.y, c0.y, fmaf(ev.z, c1.x, fmaf(ev.w, c1.y, tbf.x))));
        a1 += fmaf(ev.x, c2.x, fmaf(ev.y, c2.y, fmaf(ev.z, c3.x, fmaf(ev.w, c3.y, tbf.y))));
    }

    float v0 = 0.f, v1 = 0.f;
    if (n < N_NODES) {
        float inv = 1.0f / fmaxf((float)deg, 1.0f);
        float2 r = *reinterpret_cast<const float2*>(g_r + (size_t)n * 16 + j * 2);
        v0 = fmaf(a0, inv, r.x);
        v1 = fmaf(a1, inv, r.y);
        *reinterpret_cast<float2*>(out + (size_t)n * 16 + j * 2) = make_float2(v0, v1);
    }

    // BN stats: outputs o = 2j, 2j+1
    float s1a = v0, s1b = v1;
    float s2a = v0 * v0, s2b = v1 * v1;
    // combine lanes with same (lane & 7): xor 8, 16
#pragma unroll
    for (int m = 8; m <= 16; m <<= 1) {
        s1a += __shfl_xor_sync(0xffffffffu, s1a, m);
        s1b += __shfl_xor_sync(0xffffffffu, s1b, m);
        s2a += __shfl_xor_sync(0xffffffffu, s2a, m);
        s2b += __shfl_xor_sync(0xffffffffu, s2b, m);
    }
    __shared__ float sm1[8][8][2];
    __shared__ float sm2[8][8][2];
    int warp = t >> 5;
    int lane = t & 31;
    if (lane < 8) {
        sm1[warp][lane][0] = s1a; sm1[warp][lane][1] = s1b;
        sm2[warp][lane][0] = s2a; sm2[warp][lane][1] = s2b;
    }
    __syncthreads();
    if (t < 16) {       // o = t; j = t>>1, comp = t&1
        float r1 = 0.f, r2 = 0.f;
#pragma unroll
        for (int w = 0; w < 8; w++) {
            r1 += sm1[w][t >> 1][t & 1];
            r2 += sm2[w][t >> 1][t & 1];
        }
        atomicAdd(&g_s1[t], r1);
        atomicAdd(&g_s2[t], r2);
    }
}

// ---------------------------------------------------------------------------
// K7: BatchNorm (batch stats) + LeakyReLU, float4 in-place.
// ---------------------------------------------------------------------------
__global__ void __launch_bounds__(256) k_bn(
    float* __restrict__ out,
    const float* __restrict__ gamma,
    const float* __restrict__ beta)
{
    int i = blockIdx.x * 256 + threadIdx.x;
    if (i >= N_NODES * 4) return;
    int ob = (i & 3) * 4;
    const float invN = 1.0f / (float)N_NODES;

    float4* o4 = reinterpret_cast<float4*>(out);
    float4 val = o4[i];
    float vin[4] = {val.x, val.y, val.z, val.w};
    float res[4];
#pragma unroll
    for (int k = 0; k < 4; k++) {
        int o = ob + k;
        float mu = g_s1[o] * invN;
        float var = g_s2[o] * invN - mu * mu;
        float x = gamma[o] * (vin[k] - mu) * rsqrtf(var + 1e-5f) + beta[o];
        res[k] = (x >= 0.0f) ? x : 0.01f * x;
    }
    o4[i] = make_float4(res[0], res[1], res[2], res[3]);
}

// ---------------------------------------------------------------------------
extern "C" void kernel_launch(void* const* d_in, const int* in_sizes, int n_in,
                              void* d_out, int out_size) {
    const float* v      = (const float*)d_in[0];
    const float* e      = (const float*)d_in[1];
    const int*   ei     = (const int*)  d_in[2];
    const float* enet_w = (const float*)d_in[3];
    const float* enet_b = (const float*)d_in[4];
    const float* root   = (const float*)d_in[5];
    const float* bias   = (const float*)d_in[6];
    const float* gamma  = (const float*)d_in[7];
    const float* beta   = (const float*)d_in[8];
    float* out = (float*)d_out;

    k_zero    <<<(N_NODES + 255) / 256, 256>>>();
    k_node_pre<<<(N_NODES + 15) / 16, 256>>>(v, enet_w, enet_b, root, bias);
    k_hist    <<<(N_EDGES + 255) / 256, 256>>>(ei);
    k_scan1   <<<NB_SCAN, 1024>>>();
    k_fixup   <<<NB_SCAN, 1024>>>();
    k_scatter <<<(N_EDGES + 255) / 256, 256>>>(ei);
    k_gather  <<<(N_NODES * 8 + 255) / 256, 256>>>(e, out);
    k_bn      <<<(N_NODES * 4 + 255) / 256, 256>>>(out, gamma, beta);
}

// round 4
// speedup vs baseline: 1.0008x; 1.0008x over previous
#include <cuda_runtime.h>
#include <cuda_fp16.h>

#define N_NODES 100000
#define N_EDGES 1000000
#define NB_SCAN 98      // ceil(100000 / 1024)

__device__ __half g_t[N_NODES * 64];     // [n][o][c] fp16
__device__ __half g_tb[N_NODES * 16];    // [n][o]    fp16
__device__ float  g_r[N_NODES * 16];     // [n][o]    fp32: v@root + bias
__device__ int    g_deg[N_NODES];
__device__ int    g_rowstart[N_NODES];
__device__ int    g_cursor[N_NODES];
__device__ int    g_blocksum[NB_SCAN];
__device__ uint2  g_perm[N_EDGES];       // {src, eid} sorted by dst
__device__ float  g_s1[16];
__device__ float  g_s2[16];

// ---------------------------------------------------------------------------
// K0: zero degree histogram + BN stats
// ---------------------------------------------------------------------------
__global__ void __launch_bounds__(256) k_zero() {
    int idx = blockIdx.x * 256 + threadIdx.x;
    if (idx < N_NODES) g_deg[idx] = 0;
    if (idx < 16) { g_s1[idx] = 0.0f; g_s2[idx] = 0.0f; }
}

// ---------------------------------------------------------------------------
// K1: per-node precompute of t (fp16), tb (fp16), r = v@root + bias (fp32).
// ---------------------------------------------------------------------------
__global__ void __launch_bounds__(256) k_node_pre(
    const float* __restrict__ v,
    const float* __restrict__ enet_w,   // [256][4]
    const float* __restrict__ enet_b,   // [256]
    const float* __restrict__ root,     // [16][16] (i,o)
    const float* __restrict__ bias)     // [16]
{
    __shared__ float sw[1024];
    __shared__ float sb[256];
    __shared__ float sroot[256];
    __shared__ float sv[256];
    int t = threadIdx.x;
    for (int i = t; i < 1024; i += 256) sw[i] = enet_w[i];
    sb[t] = enet_b[t];
    sroot[t] = root[t];
    int nbase = blockIdx.x * 16;
    sv[t] = v[nbase * 16 + t];
    __syncthreads();

    int nl = t >> 4;
    int o = t & 15;
    int n = nbase + nl;
    if (n >= N_NODES) return;

    float a0 = 0.f, a1 = 0.f, a2 = 0.f, a3 = 0.f, ab = 0.f, ar = bias[o];
    const float* vrow = sv + nl * 16;
#pragma unroll
    for (int i = 0; i < 16; i++) {
        float vi = vrow[i];
        int j = i * 16 + o;
        const float* w4 = sw + j * 4;
        a0 = fmaf(vi, w4[0], a0);
        a1 = fmaf(vi, w4[1], a1);
        a2 = fmaf(vi, w4[2], a2);
        a3 = fmaf(vi, w4[3], a3);
        ab = fmaf(vi, sb[j], ab);
        ar = fmaf(vi, sroot[j], ar);
    }
    __half2 h01 = __floats2half2_rn(a0, a1);
    __half2 h23 = __floats2half2_rn(a2, a3);
    uint2 pk;
    pk.x = *reinterpret_cast<unsigned*>(&h01);
    pk.y = *reinterpret_cast<unsigned*>(&h23);
    *reinterpret_cast<uint2*>(g_t + (size_t)n * 64 + o * 4) = pk;
    g_tb[n * 16 + o] = __float2half_rn(ab);
    g_r[n * 16 + o] = ar;
}

// ---------------------------------------------------------------------------
// K2: degree histogram over dst
// ---------------------------------------------------------------------------
__global__ void __launch_bounds__(256) k_hist(const int* __restrict__ ei) {
    int e = blockIdx.x * 256 + threadIdx.x;
    if (e < N_EDGES) atomicAdd(&g_deg[ei[N_EDGES + e]], 1);
}

// ---------------------------------------------------------------------------
// K3: per-block exclusive scan of degrees (1024-elem chunks)
// ---------------------------------------------------------------------------
__global__ void __launch_bounds__(1024) k_scan1() {
    __shared__ int s[1024];
    int t = threadIdx.x;
    int i = blockIdx.x * 1024 + t;
    int v = (i < N_NODES) ? g_deg[i] : 0;
    s[t] = v;
    __syncthreads();
#pragma unroll
    for (int off = 1; off < 1024; off <<= 1) {
        int x = (t >= off) ? s[t - off] : 0;
        __syncthreads();
        s[t] += x;
        __syncthreads();
    }
    if (i < N_NODES) g_rowstart[i] = s[t] - v;     // exclusive
    if (t == 1023) g_blocksum[blockIdx.x] = s[t];
}

// ---------------------------------------------------------------------------
// K4: add cross-block offsets; materialize rowstart + cursor
// ---------------------------------------------------------------------------
__global__ void __launch_bounds__(1024) k_fixup() {
    __shared__ int sb[128];
    int b = blockIdx.x;
    int t = threadIdx.x;
    if (t < 128) sb[t] = (t < b && t < NB_SCAN) ? g_blocksum[t] : 0;
    __syncthreads();
#pragma unroll
    for (int s = 64; s >= 1; s >>= 1) {
        if (t < s) sb[t] += sb[t + s];
        __syncthreads();
    }
    int i = b * 1024 + t;
    if (i < N_NODES) {
        int rs = g_rowstart[i] + sb[0];
        g_rowstart[i] = rs;
        g_cursor[i] = rs;
    }
}

// ---------------------------------------------------------------------------
// K5: scatter {src, eid} into dst-sorted perm array
// ---------------------------------------------------------------------------
__global__ void __launch_bounds__(256) k_scatter(const int* __restrict__ ei) {
    int e = blockIdx.x * 256 + threadIdx.x;
    if (e >= N_EDGES) return;
    int src = ei[e];
    int dst = ei[N_EDGES + e];
    int pos = atomicAdd(&g_cursor[dst], 1);
    g_perm[pos] = make_uint2((unsigned)src, (unsigned)e);
}

// ---------------------------------------------------------------------------
// K6: gather — 8 threads per node, each accumulates outputs o=2j, 2j+1.
// Replaces edge-RED + finalize: out = msg_sum/max(deg,1) + r; BN stats inline.
// ---------------------------------------------------------------------------
__global__ void __launch_bounds__(256) k_gather(
    const float* __restrict__ efeat,
    float* __restrict__ out)
{
    int t = threadIdx.x;
    int gid = blockIdx.x * 256 + t;
    int n = gid >> 3;
    int j = gid & 7;          // == t & 7 (256 % 8 == 0)

    float a0 = 0.f, a1 = 0.f;
    int beg = 0, deg = 0;
    if (n < N_NODES) { beg = g_rowstart[n]; deg = g_deg[n]; }
    int end = beg + deg;

    const float4* ef4 = reinterpret_cast<const float4*>(efeat);

    uint2 es = (deg > 0) ? g_perm[beg] : make_uint2(0u, 0u);
    for (int p = beg; p < end; p++) {
        uint2 cur = es;
        int pn = p + 1;
        if (pn < end) es = g_perm[pn];                 // prefetch next
        float4 ev = __ldg(ef4 + cur.y);
        uint4 traw = __ldg(reinterpret_cast<const uint4*>(g_t + (size_t)cur.x * 64 + j * 8));
        unsigned tbraw = __ldg(reinterpret_cast<const unsigned*>(g_tb + (size_t)cur.x * 16 + j * 2));
        __half2 h0 = *reinterpret_cast<__half2*>(&traw.x);
        __half2 h1 = *reinterpret_cast<__half2*>(&traw.y);
        __half2 h2 = *reinterpret_cast<__half2*>(&traw.z);
        __half2 h3 = *reinterpret_cast<__half2*>(&traw.w);
        __half2 tbh = *reinterpret_cast<__half2*>(&tbraw);
        float2 c0 = __half22float2(h0);
        float2 c1 = __half22float2(h1);
        float2 c2 = __half22float2(h2);
        float2 c3 = __half22float2(h3);
        float2 tbf = __half22float2(tbh);
        a0 += fmaf(ev.x, c0.x, fmaf(ev.y, c0.y, fmaf(ev.z, c1.x, fmaf(ev.w, c1.y, tbf.x))));
        a1 += fmaf(ev.x, c2.x, fmaf(ev.y, c2.y, fmaf(ev.z, c3.x, fmaf(ev.w, c3.y, tbf.y))));
    }

    float v0 = 0.f, v1 = 0.f;
    if (n < N_NODES) {
        float inv = 1.0f / fmaxf((float)deg, 1.0f);
        float2 r = *reinterpret_cast<const float2*>(g_r + (size_t)n * 16 + j * 2);
        v0 = fmaf(a0, inv, r.x);
        v1 = fmaf(a1, inv, r.y);
        *reinterpret_cast<float2*>(out + (size_t)n * 16 + j * 2) = make_float2(v0, v1);
    }

    // BN stats: outputs o = 2j, 2j+1
    float s1a = v0, s1b = v1;
    float s2a = v0 * v0, s2b = v1 * v1;
    // combine lanes with same (lane & 7): xor 8, 16
#pragma unroll
    for (int m = 8; m <= 16; m <<= 1) {
        s1a += __shfl_xor_sync(0xffffffffu, s1a, m);
        s1b += __shfl_xor_sync(0xffffffffu, s1b, m);
        s2a += __shfl_xor_sync(0xffffffffu, s2a, m);
        s2b += __shfl_xor_sync(0xffffffffu, s2b, m);
    }
    __shared__ float sm1[8][8][2];
    __shared__ float sm2[8][8][2];
    int warp = t >> 5;
    int lane = t & 31;
    if (lane < 8) {
        sm1[warp][lane][0] = s1a; sm1[warp][lane][1] = s1b;
        sm2[warp][lane][0] = s2a; sm2[warp][lane][1] = s2b;
    }
    __syncthreads();
    if (t < 16) {       // o = t; j = t>>1, comp = t&1
        float r1 = 0.f, r2 = 0.f;
#pragma unroll
        for (int w = 0; w < 8; w++) {
            r1 += sm1[w][t >> 1][t & 1];
            r2 += sm2[w][t >> 1][t & 1];
        }
        atomicAdd(&g_s1[t], r1);
        atomicAdd(&g_s2[t], r2);
    }
}

// ---------------------------------------------------------------------------
// K7: BatchNorm (batch stats) + LeakyReLU, float4 in-place.
// ---------------------------------------------------------------------------
__global__ void __launch_bounds__(256) k_bn(
    float* __restrict__ out,
    const float* __restrict__ gamma,
    const float* __restrict__ beta)
{
    int i = blockIdx.x * 256 + threadIdx.x;
    if (i >= N_NODES * 4) return;
    int ob = (i & 3) * 4;
    const float invN = 1.0f / (float)N_NODES;

    float4* o4 = reinterpret_cast<float4*>(out);
    float4 val = o4[i];
    float vin[4] = {val.x, val.y, val.z, val.w};
    float res[4];
#pragma unroll
    for (int k = 0; k < 4; k++) {
        int o = ob + k;
        float mu = g_s1[o] * invN;
        float var = g_s2[o] * invN - mu * mu;
        float x = gamma[o] * (vin[k] - mu) * rsqrtf(var + 1e-5f) + beta[o];
        res[k] = (x >= 0.0f) ? x : 0.01f * x;
    }
    o4[i] = make_float4(res[0], res[1], res[2], res[3]);
}

// ---------------------------------------------------------------------------
extern "C" void kernel_launch(void* const* d_in, const int* in_sizes, int n_in,
                              void* d_out, int out_size) {
    const float* v      = (const float*)d_in[0];
    const float* e      = (const float*)d_in[1];
    const int*   ei     = (const int*)  d_in[2];
    const float* enet_w = (const float*)d_in[3];
    const float* enet_b = (const float*)d_in[4];
    const float* root   = (const float*)d_in[5];
    const float* bias   = (const float*)d_in[6];
    const float* gamma  = (const float*)d_in[7];
    const float* beta   = (const float*)d_in[8];
    float* out = (float*)d_out;

    k_zero    <<<(N_NODES + 255) / 256, 256>>>();
    k_node_pre<<<(N_NODES + 15) / 16, 256>>>(v, enet_w, enet_b, root, bias);
    k_hist    <<<(N_EDGES + 255) / 256, 256>>>(ei);
    k_scan1   <<<NB_SCAN, 1024>>>();
    k_fixup   <<<NB_SCAN, 1024>>>();
    k_scatter <<<(N_EDGES + 255) / 256, 256>>>(ei);
    k_gather  <<<(N_NODES * 8 + 255) / 256, 256>>>(e, out);
    k_bn      <<<(N_NODES * 4 + 255) / 256, 256>>>(out, gamma, beta);
}